// round 14
// baseline (speedup 1.0000x reference)
#include <cuda_runtime.h>
#include <cuda_bf16.h>
#include <cuda_fp16.h>
#include <math.h>

// Problem constants
#define NMAX   50000
#define EMAX   600000
#define FIN    74
#define KIN    80          // FIN padded to multiple of 16
#define HDIM   128
#define NG     500
#define SCHUNK 1024        // nodes per scan block
#define NBMAX  64

// ---------------- scratch (device globals) ----------------
__device__ __align__(16) __half g_h0[NMAX * HDIM];          // node features ping (fp16)
__device__ __align__(16) __half g_h1[NMAX * HDIM];          // node features pong (fp16)
__device__ __align__(16) __nv_bfloat16 g_ahi[NMAX * HDIM];  // GEMM A operand hi
__device__ __align__(16) __nv_bfloat16 g_alo[NMAX * HDIM];  // GEMM A operand lo
// transposed weights: Wt[n][k].  in: 128*80, g0/g1/g2: 128*128 each
#define WT_IN_OFF  0
#define WT_G_OFF   (128*KIN)
#define WT_TOTAL   (128*KIN + 3*128*128)
__device__ __align__(16) __nv_bfloat16 g_wthi[WT_TOTAL];
__device__ __align__(16) __nv_bfloat16 g_wtlo[WT_TOTAL];

__device__ int   g_outcnt[NMAX];
__device__ int   g_incnt[NMAX];
__device__ int   g_rowptr[NMAX + 1];
__device__ int   g_fill[NMAX];
__device__ int   g_col[EMAX];
__device__ float g_outnorm[NMAX];
__device__ float g_innorm[NMAX];
__device__ __align__(16) float g_pooled[NG * HDIM];
__device__ int   g_gcnt[NG];
__device__ int   g_bsum[NBMAX];
__device__ int   g_boff[NBMAX];

// ---------------- init ----------------
__global__ void k_init(int N) {
    int i = blockIdx.x * blockDim.x + threadIdx.x;
    if (i < N) { g_outcnt[i] = 0; g_incnt[i] = 0; }
    if (i < NG * HDIM) g_pooled[i] = 0.0f;
    if (i < NG) g_gcnt[i] = 0;
}

// ---------------- degree histogram ----------------
__global__ void k_hist(const int* __restrict__ src, const int* __restrict__ dst, int E) {
    int i = blockIdx.x * blockDim.x + threadIdx.x;
    if (i < E) {
        atomicAdd(&g_outcnt[src[i]], 1);
        atomicAdd(&g_incnt[dst[i]], 1);
    }
}

// ---------------- parallel scan, phase 1: per-block reduce + norms ----------
__global__ void __launch_bounds__(256) k_scan1(int N) {
    int b = blockIdx.x, t = threadIdx.x;
    int i0 = b * SCHUNK + t * 4;
    int s = 0;
#pragma unroll
    for (int j = 0; j < 4; ++j) {
        int i = i0 + j;
        if (i < N) {
            int c = g_incnt[i];
            s += c;
            g_innorm[i] = rsqrtf((float)(c > 0 ? c : 1));
            int oc = g_outcnt[i];
            g_outnorm[i] = rsqrtf((float)(oc > 0 ? oc : 1));
        }
    }
    __shared__ int red[8];
#pragma unroll
    for (int o = 16; o; o >>= 1) s += __shfl_down_sync(~0u, s, o);
    if ((t & 31) == 0) red[t >> 5] = s;
    __syncthreads();
    if (t < 8) {
        int v = red[t];
#pragma unroll
        for (int o = 4; o; o >>= 1) v += __shfl_down_sync(0xffu, v, o);
        if (t == 0) g_bsum[b] = v;
    }
}

// ---------------- scan phase 2: scan block sums (tiny) ----------------
__global__ void k_scan2(int NB, int N) {
    int t = threadIdx.x;  // 64 threads
    int v = (t < NB) ? g_bsum[t] : 0;
    __shared__ int sh[64];
    sh[t] = v;
    __syncthreads();
    for (int o = 1; o < 64; o <<= 1) {
        int u = (t >= o) ? sh[t - o] : 0;
        __syncthreads();
        sh[t] += u;
        __syncthreads();
    }
    if (t < NB) g_boff[t] = sh[t] - v;  // exclusive
    if (t == 63) g_rowptr[N] = sh[63];
}

// ---------------- scan phase 3: per-block rescan, write rowptr/fill --------
__global__ void __launch_bounds__(256) k_scan3(int N) {
    int b = blockIdx.x, t = threadIdx.x;
    int lane = t & 31, w = t >> 5;
    int i0 = b * SCHUNK + t * 4;
    int c[4];
    int s = 0;
#pragma unroll
    for (int j = 0; j < 4; ++j) {
        int i = i0 + j;
        c[j] = (i < N) ? g_incnt[i] : 0;
        s += c[j];
    }
    int pre = s;
#pragma unroll
    for (int o = 1; o < 32; o <<= 1) {
        int u = __shfl_up_sync(~0u, pre, o);
        if (lane >= o) pre += u;
    }
    __shared__ int wsum[8];
    if (lane == 31) wsum[w] = pre;
    __syncthreads();
    if (t < 8) {
        int v = wsum[t];
#pragma unroll
        for (int o = 1; o < 8; o <<= 1) {
            int u = __shfl_up_sync(0xffu, v, o);
            if ((int)t >= o) v += u;
        }
        wsum[t] = v;
    }
    __syncthreads();
    int base = g_boff[b] + (w ? wsum[w - 1] : 0) + (pre - s);
#pragma unroll
    for (int j = 0; j < 4; ++j) {
        int i = i0 + j;
        if (i < N) {
            g_rowptr[i] = base;
            g_fill[i]   = base;
            base += c[j];
        }
    }
}

// ---------------- CSR placement ----------------
__global__ void k_fill(const int* __restrict__ src, const int* __restrict__ dst, int E) {
    int i = blockIdx.x * blockDim.x + threadIdx.x;
    if (i < E) {
        int d = dst[i];
        int p = atomicAdd(&g_fill[d], 1);
        g_col[p] = src[i];
    }
}

// ---------------- hi/lo split helpers ----------------
__device__ __forceinline__ void split_bf(float v, __nv_bfloat16& hi, __nv_bfloat16& lo) {
    hi = __float2bfloat16_rn(v);
    lo = __float2bfloat16_rn(v - __bfloat162float(hi));
}
__device__ __forceinline__ unsigned pack2(__nv_bfloat16 a, __nv_bfloat16 b) {
    return ((unsigned)__bfloat16_as_ushort(b) << 16) | (unsigned)__bfloat16_as_ushort(a);
}

// ---------------- prep: transpose + split weights (small) ----------------
__global__ void k_prepw(const float* __restrict__ Win,
                        const float* __restrict__ Wg0,
                        const float* __restrict__ Wg1,
                        const float* __restrict__ Wg2) {
    int i = blockIdx.x * blockDim.x + threadIdx.x;
    if (i < 128 * KIN) {
        int n = i / KIN, k = i % KIN;
        float v = (k < FIN) ? Win[k * 128 + n] : 0.0f;
        split_bf(v, g_wthi[WT_IN_OFF + i], g_wtlo[WT_IN_OFF + i]);
    } else if (i < 128 * KIN + 3 * 128 * 128) {
        int j = i - 128 * KIN;
        int l = j / (128 * 128);
        int r = j - l * 128 * 128;
        int n = r / 128, k = r % 128;
        const float* W = (l == 0) ? Wg0 : (l == 1) ? Wg1 : Wg2;
        float v = W[k * 128 + n];
        split_bf(v, g_wthi[WT_G_OFF + j], g_wtlo[WT_G_OFF + j]);
    }
}

// ---------------- tensor-core GEMM + bias + SiLU (+outnorm) -> fp16 --------
// MODE 0: A = x[N,FIN] fp32, padded to KP, split in staging.
// MODE 2: A = pre-split bf16 hi/lo buffers (from k_agg).
// out[r,:] = fp16( silu(A @ W + b) * (PREMUL ? outnorm[r] : 1) )
// Block: 256 thr (8 warps = 2M x 4N), tile 64 rows x 128 cols. (R6 config)
__device__ __forceinline__ float silu1(float v) { return v / (1.0f + __expf(-v)); }

__device__ __forceinline__ void mma16816(float* d, const unsigned* a, const unsigned* b) {
    asm volatile(
        "mma.sync.aligned.m16n8k16.row.col.f32.bf16.bf16.f32 "
        "{%0,%1,%2,%3}, {%4,%5,%6,%7}, {%8,%9}, {%0,%1,%2,%3};"
        : "+f"(d[0]), "+f"(d[1]), "+f"(d[2]), "+f"(d[3])
        : "r"(a[0]), "r"(a[1]), "r"(a[2]), "r"(a[3]), "r"(b[0]), "r"(b[1]));
}

template <int KP, int MODE, bool PREMUL>
__global__ void __launch_bounds__(256)
k_mlp(const float* __restrict__ Ax,
      const __nv_bfloat16* __restrict__ Ahi, const __nv_bfloat16* __restrict__ Alo,
      const __nv_bfloat16* __restrict__ Whi, const __nv_bfloat16* __restrict__ Wlo,
      const float* __restrict__ bias, __half* __restrict__ out, int N) {
    constexpr int SW = KP / 2 + 4;             // padded stride in 32-bit words
    constexpr int AW = 64 * SW;
    constexpr int WW = 128 * SW;
    extern __shared__ unsigned sh[];
    unsigned* sAh = sh;
    unsigned* sAl = sh + AW;
    unsigned* sWh = sh + 2 * AW;
    unsigned* sWl = sh + 2 * AW + WW;

    const int tid  = threadIdx.x;
    const int lane = tid & 31;
    const int gid  = lane >> 2;
    const int tig  = lane & 3;
    const int warp = tid >> 5;
    const int wm   = warp & 1;
    const int wn   = warp >> 1;
    const int r0   = blockIdx.x * 64;

    // stage W (transposed [n][k], uint4 = 8 bf16)
    constexpr int ACH = KP / 8;
    for (int i = tid; i < 128 * ACH; i += 256) {
        int n = i / ACH, c = i - n * ACH;
        *reinterpret_cast<uint4*>(sWh + n * SW + c * 4) =
            reinterpret_cast<const uint4*>(Whi + (size_t)n * KP)[c];
        *reinterpret_cast<uint4*>(sWl + n * SW + c * 4) =
            reinterpret_cast<const uint4*>(Wlo + (size_t)n * KP)[c];
    }

    // stage A
    if constexpr (MODE == 0) {
        for (int i = tid; i < 64 * (KP / 2); i += 256) {
            int r = i / (KP / 2), kw = i - r * (KP / 2);
            int k = kw * 2, gr = r0 + r;
            float v0 = 0.f, v1 = 0.f;
            if (gr < N) {
                if (k < FIN)     v0 = Ax[(size_t)gr * FIN + k];
                if (k + 1 < FIN) v1 = Ax[(size_t)gr * FIN + k + 1];
            }
            __nv_bfloat16 h0, l0, h1, l1;
            split_bf(v0, h0, l0); split_bf(v1, h1, l1);
            sAh[r * SW + kw] = pack2(h0, h1);
            sAl[r * SW + kw] = pack2(l0, l1);
        }
    } else {
        for (int i = tid; i < 64 * ACH; i += 256) {
            int r = i / ACH, c = i - r * ACH;
            int gr = r0 + r;
            uint4 vh = make_uint4(0, 0, 0, 0), vl = vh;
            if (gr < N) {
                vh = reinterpret_cast<const uint4*>(Ahi + (size_t)gr * KP)[c];
                vl = reinterpret_cast<const uint4*>(Alo + (size_t)gr * KP)[c];
            }
            *reinterpret_cast<uint4*>(sAh + r * SW + c * 4) = vh;
            *reinterpret_cast<uint4*>(sAl + r * SW + c * 4) = vl;
        }
    }
    __syncthreads();

    float d[2][4][4];
#pragma unroll
    for (int nt = 0; nt < 4; ++nt) {
        int c = wn * 32 + nt * 8 + tig * 2;
        float b0 = bias[c], b1 = bias[c + 1];
#pragma unroll
        for (int mi = 0; mi < 2; ++mi) {
            d[mi][nt][0] = b0; d[mi][nt][1] = b1;
            d[mi][nt][2] = b0; d[mi][nt][3] = b1;
        }
    }

#pragma unroll
    for (int ks = 0; ks < KP / 16; ++ks) {
        unsigned ah[2][4], al[2][4];
#pragma unroll
        for (int mi = 0; mi < 2; ++mi) {
            int rr = wm * 32 + mi * 16 + gid;
            int base = ks * 8 + tig;
            ah[mi][0] = sAh[rr * SW + base];
            ah[mi][1] = sAh[(rr + 8) * SW + base];
            ah[mi][2] = sAh[rr * SW + base + 4];
            ah[mi][3] = sAh[(rr + 8) * SW + base + 4];
            al[mi][0] = sAl[rr * SW + base];
            al[mi][1] = sAl[(rr + 8) * SW + base];
            al[mi][2] = sAl[rr * SW + base + 4];
            al[mi][3] = sAl[(rr + 8) * SW + base + 4];
        }
#pragma unroll
        for (int nt = 0; nt < 4; ++nt) {
            int n = wn * 32 + nt * 8 + gid;
            int base = n * SW + ks * 8 + tig;
            unsigned bh[2], bl[2];
            bh[0] = sWh[base]; bh[1] = sWh[base + 4];
            bl[0] = sWl[base]; bl[1] = sWl[base + 4];
#pragma unroll
            for (int mi = 0; mi < 2; ++mi) {
                mma16816(d[mi][nt], ah[mi], bh);
                mma16816(d[mi][nt], ah[mi], bl);
                mma16816(d[mi][nt], al[mi], bh);
            }
        }
    }

    // epilogue: silu (+outnorm premul) + store fp16
#pragma unroll
    for (int mi = 0; mi < 2; ++mi) {
        int r1 = r0 + wm * 32 + mi * 16 + gid;
        int r2 = r1 + 8;
        float on1 = 1.f, on2 = 1.f;
        if (PREMUL) {
            if (r1 < N) on1 = g_outnorm[r1];
            if (r2 < N) on2 = g_outnorm[r2];
        }
#pragma unroll
        for (int nt = 0; nt < 4; ++nt) {
            int c = wn * 32 + nt * 8 + tig * 2;
            if (r1 < N) {
                __half2 v = __floats2half2_rn(silu1(d[mi][nt][0]) * on1,
                                              silu1(d[mi][nt][1]) * on1);
                *reinterpret_cast<__half2*>(out + (size_t)r1 * 128 + c) = v;
            }
            if (r2 < N) {
                __half2 v = __floats2half2_rn(silu1(d[mi][nt][2]) * on2,
                                              silu1(d[mi][nt][3]) * on2);
                *reinterpret_cast<__half2*>(out + (size_t)r2 * 128 + c) = v;
            }
        }
    }
}

// ---------------- gather-aggregate (fp16 in) -> bf16 hi/lo -----------------
// A[w,:] = innorm[w] * sum_{e in row w} h[col[e], :]   (outnorm pre-applied)
__global__ void k_agg(const __half* __restrict__ h, int N) {
    int w = (blockIdx.x * blockDim.x + threadIdx.x) >> 5;
    int lane = threadIdx.x & 31;
    if (w >= N) return;
    int e0 = g_rowptr[w], e1 = g_rowptr[w + 1];
    const uint2* hu = reinterpret_cast<const uint2*>(h);  // 4 halves per lane
    float4 a0 = make_float4(0.f, 0.f, 0.f, 0.f);
    float4 a1 = a0;
    int e = e0;
    for (; e + 1 < e1; e += 2) {
        int s0 = g_col[e], s1 = g_col[e + 1];
        uint2 u0 = hu[(size_t)s0 * 32 + lane];
        uint2 u1 = hu[(size_t)s1 * 32 + lane];
        float2 p0 = __half22float2(*reinterpret_cast<__half2*>(&u0.x));
        float2 p1 = __half22float2(*reinterpret_cast<__half2*>(&u0.y));
        float2 q0 = __half22float2(*reinterpret_cast<__half2*>(&u1.x));
        float2 q1 = __half22float2(*reinterpret_cast<__half2*>(&u1.y));
        a0.x += p0.x; a0.y += p0.y; a0.z += p1.x; a0.w += p1.y;
        a1.x += q0.x; a1.y += q0.y; a1.z += q1.x; a1.w += q1.y;
    }
    if (e < e1) {
        int s = g_col[e];
        uint2 u = hu[(size_t)s * 32 + lane];
        float2 p0 = __half22float2(*reinterpret_cast<__half2*>(&u.x));
        float2 p1 = __half22float2(*reinterpret_cast<__half2*>(&u.y));
        a0.x += p0.x; a0.y += p0.y; a0.z += p1.x; a0.w += p1.y;
    }
    float inn = g_innorm[w];
    float o[4] = {(a0.x + a1.x) * inn, (a0.y + a1.y) * inn,
                  (a0.z + a1.z) * inn, (a0.w + a1.w) * inn};
    __nv_bfloat16 hi[4], lo[4];
#pragma unroll
    for (int j = 0; j < 4; ++j) split_bf(o[j], hi[j], lo[j]);
    size_t base = (size_t)w * 128 + lane * 4;
    *reinterpret_cast<__nv_bfloat162*>(g_ahi + base)     = __nv_bfloat162(hi[0], hi[1]);
    *reinterpret_cast<__nv_bfloat162*>(g_ahi + base + 2) = __nv_bfloat162(hi[2], hi[3]);
    *reinterpret_cast<__nv_bfloat162*>(g_alo + base)     = __nv_bfloat162(lo[0], lo[1]);
    *reinterpret_cast<__nv_bfloat162*>(g_alo + base + 2) = __nv_bfloat162(lo[2], lo[3]);
}

// ---------------- segment-sum pooling (graph_ids sorted, fp16 in) ----------
__global__ void k_pool(const __half* __restrict__ h, const int* __restrict__ gid, int N) {
    int r0 = blockIdx.x * 128;
    if (r0 >= N) return;
    int r1 = r0 + 128; if (r1 > N) r1 = N;
    int j = threadIdx.x;
    int cur = gid[r0];
    float acc = 0.0f;
    int run = 0;
    for (int r = r0; r < r1; ++r) {
        int g = gid[r];
        if (g != cur) {
            atomicAdd(&g_pooled[cur * HDIM + j], acc);
            if (j == 0) atomicAdd(&g_gcnt[cur], run);
            acc = 0.0f; run = 0; cur = g;
        }
        acc += __half2float(h[(size_t)r * HDIM + j]);
        ++run;
    }
    atomicAdd(&g_pooled[cur * HDIM + j], acc);
    if (j == 0) atomicAdd(&g_gcnt[cur], run);
}

// ---------------- final: (pooled @ W_out + cnt*b_out) @ W_ff + b_ff ----------
__global__ void k_final(const float* __restrict__ Wout, const float* __restrict__ bout,
                        const float* __restrict__ Wff, const float* __restrict__ bff,
                        float* __restrict__ out) {
    __shared__ float p[HDIM];
    __shared__ float red[HDIM];
    int g = blockIdx.x, j = threadIdx.x;
    p[j] = g_pooled[g * HDIM + j];
    __syncthreads();
    float t = (float)g_gcnt[g] * bout[j];
#pragma unroll 8
    for (int k = 0; k < HDIM; ++k)
        t = fmaf(p[k], Wout[k * HDIM + j], t);
    red[j] = t * Wff[j];
    __syncthreads();
    for (int s = 64; s > 0; s >>= 1) {
        if (j < s) red[j] += red[j + s];
        __syncthreads();
    }
    if (j == 0) out[g] = red[0] + bff[0];
}

// ---------------- launch ----------------
extern "C" void kernel_launch(void* const* d_in, const int* in_sizes, int n_in,
                              void* d_out, int out_size) {
    const float* x     = (const float*)d_in[0];
    const float* W_in  = (const float*)d_in[1];
    const float* b_in  = (const float*)d_in[2];
    const float* W_g0  = (const float*)d_in[3];
    const float* b_g0  = (const float*)d_in[4];
    const float* W_g1  = (const float*)d_in[5];
    const float* b_g1  = (const float*)d_in[6];
    const float* W_g2  = (const float*)d_in[7];
    const float* b_g2  = (const float*)d_in[8];
    const float* W_out = (const float*)d_in[9];
    const float* b_out = (const float*)d_in[10];
    const float* W_ff  = (const float*)d_in[11];
    const float* b_ff  = (const float*)d_in[12];
    const int*   src   = (const int*)d_in[13];
    const int*   dst   = (const int*)d_in[14];
    const int*   gids  = (const int*)d_in[15];
    float* out = (float*)d_out;

    const int N = in_sizes[0] / FIN;
    const int E = in_sizes[13];
    const int NB = (N + SCHUNK - 1) / SCHUNK;

    __half *h0, *h1;
    __nv_bfloat16 *ahi, *alo, *whi, *wlo;
    cudaGetSymbolAddress((void**)&h0, g_h0);
    cudaGetSymbolAddress((void**)&h1, g_h1);
    cudaGetSymbolAddress((void**)&ahi, g_ahi);
    cudaGetSymbolAddress((void**)&alo, g_alo);
    cudaGetSymbolAddress((void**)&whi, g_wthi);
    cudaGetSymbolAddress((void**)&wlo, g_wtlo);

    const int SW80  = KIN / 2 + 4;
    const int SW128 = HDIM / 2 + 4;
    const size_t shm80  = (size_t)(2 * 64 * SW80 + 2 * 128 * SW80) * 4;    // ~67.5 KB
    const size_t shm128 = (size_t)(2 * 64 * SW128 + 2 * 128 * SW128) * 4;  // ~102 KB
    cudaFuncSetAttribute(k_mlp<KIN, 0, true>,
                         cudaFuncAttributeMaxDynamicSharedMemorySize, (int)shm80);
    cudaFuncSetAttribute(k_mlp<HDIM, 2, true>,
                         cudaFuncAttributeMaxDynamicSharedMemorySize, (int)shm128);
    cudaFuncSetAttribute(k_mlp<HDIM, 2, false>,
                         cudaFuncAttributeMaxDynamicSharedMemorySize, (int)shm128);

    int initMax = (N > NG * HDIM) ? N : NG * HDIM;
    int gemm_blocks = (N + 63) / 64;

    k_prepw<<<(128 * KIN + 3 * 128 * 128 + 255) / 256, 256>>>(W_in, W_g0, W_g1, W_g2); // 0
    k_init<<<(initMax + 255) / 256, 256>>>(N);                                         // 1
    k_hist<<<(E + 255) / 256, 256>>>(src, dst, E);                                     // 2
    k_scan1<<<NB, 256>>>(N);                                                           // 3
    k_scan2<<<1, 64>>>(NB, N);                                                         // 4
    // embedding_in at slot 5 (ncu -s 5 -c 1 lands here): h0 = silu(x@Win+b)*outnorm
    k_mlp<KIN, 0, true><<<gemm_blocks, 256, shm80>>>(
        x, nullptr, nullptr, whi + WT_IN_OFF, wlo + WT_IN_OFF, b_in, h0, N);           // 5
    k_scan3<<<NB, 256>>>(N);                                                           // 6
    k_fill<<<(E + 255) / 256, 256>>>(src, dst, E);                                     // 7

    const float* bg[3] = {b_g0, b_g1, b_g2};
    __half* hin[3]  = {h0, h1, h0};
    __half* hout[3] = {h1, h0, h1};
    int agg_blocks = (N * 32 + 255) / 256;
    for (int l = 0; l < 3; ++l) {
        k_agg<<<agg_blocks, 256>>>(hin[l], N);
        if (l < 2)
            k_mlp<HDIM, 2, true><<<gemm_blocks, 256, shm128>>>(
                nullptr, ahi, alo, whi + WT_G_OFF + l * 128 * 128,
                wlo + WT_G_OFF + l * 128 * 128, bg[l], hout[l], N);
        else
            k_mlp<HDIM, 2, false><<<gemm_blocks, 256, shm128>>>(
                nullptr, ahi, alo, whi + WT_G_OFF + l * 128 * 128,
                wlo + WT_G_OFF + l * 128 * 128, bg[l], hout[l], N);
    }

    k_pool<<<(N + 127) / 128, 128>>>(h1, gids, N);
    k_final<<<NG, HDIM>>>(W_out, b_out, W_ff, b_ff, out);
}

// round 15
// speedup vs baseline: 1.0058x; 1.0058x over previous
#include <cuda_runtime.h>
#include <cuda_bf16.h>
#include <cuda_fp16.h>
#include <math.h>

// Problem constants
#define NMAX   50000
#define EMAX   600000
#define FIN    74
#define KIN    80          // FIN padded to multiple of 16
#define HDIM   128
#define NG     500
#define SCHUNK 1024        // nodes per scan block
#define NBMAX  64

// ---------------- scratch (device globals) ----------------
__device__ __align__(16) __half g_h0[NMAX * HDIM];          // node features ping (fp16)
__device__ __align__(16) __half g_h1[NMAX * HDIM];          // node features pong (fp16)
__device__ __align__(16) __nv_bfloat16 g_ahi[NMAX * HDIM];  // GEMM A operand hi
__device__ __align__(16) __nv_bfloat16 g_alo[NMAX * HDIM];  // GEMM A operand lo
// transposed weights: Wt[n][k].  in: 128*80, g0/g1/g2: 128*128 each
#define WT_IN_OFF  0
#define WT_G_OFF   (128*KIN)
#define WT_TOTAL   (128*KIN + 3*128*128)
__device__ __align__(16) __nv_bfloat16 g_wthi[WT_TOTAL];
__device__ __align__(16) __nv_bfloat16 g_wtlo[WT_TOTAL];

__device__ int   g_outcnt[NMAX];
__device__ int   g_incnt[NMAX];
__device__ int   g_rowptr[NMAX + 1];
__device__ int   g_fill[NMAX];
__device__ int   g_col[EMAX];
__device__ float g_outnorm[NMAX];
__device__ float g_innorm[NMAX];
__device__ __align__(16) float g_pooled[NG * HDIM];
__device__ int   g_gcnt[NG];
__device__ int   g_bsum[NBMAX];
__device__ int   g_boff[NBMAX];

// ---------------- init ----------------
__global__ void k_init(int N) {
    int i = blockIdx.x * blockDim.x + threadIdx.x;
    if (i < N) { g_outcnt[i] = 0; g_incnt[i] = 0; }
    if (i < NG * HDIM) g_pooled[i] = 0.0f;
    if (i < NG) g_gcnt[i] = 0;
}

// ---------------- degree histogram ----------------
__global__ void k_hist(const int* __restrict__ src, const int* __restrict__ dst, int E) {
    int i = blockIdx.x * blockDim.x + threadIdx.x;
    if (i < E) {
        atomicAdd(&g_outcnt[src[i]], 1);
        atomicAdd(&g_incnt[dst[i]], 1);
    }
}

// ---------------- parallel scan, phase 1: per-block reduce + norms ----------
__global__ void __launch_bounds__(256) k_scan1(int N) {
    int b = blockIdx.x, t = threadIdx.x;
    int i0 = b * SCHUNK + t * 4;
    int s = 0;
#pragma unroll
    for (int j = 0; j < 4; ++j) {
        int i = i0 + j;
        if (i < N) {
            int c = g_incnt[i];
            s += c;
            g_innorm[i] = rsqrtf((float)(c > 0 ? c : 1));
            int oc = g_outcnt[i];
            g_outnorm[i] = rsqrtf((float)(oc > 0 ? oc : 1));
        }
    }
    __shared__ int red[8];
#pragma unroll
    for (int o = 16; o; o >>= 1) s += __shfl_down_sync(~0u, s, o);
    if ((t & 31) == 0) red[t >> 5] = s;
    __syncthreads();
    if (t < 8) {
        int v = red[t];
#pragma unroll
        for (int o = 4; o; o >>= 1) v += __shfl_down_sync(0xffu, v, o);
        if (t == 0) g_bsum[b] = v;
    }
}

// ---------------- scan phase 2: scan block sums (tiny) ----------------
__global__ void k_scan2(int NB, int N) {
    int t = threadIdx.x;  // 64 threads
    int v = (t < NB) ? g_bsum[t] : 0;
    __shared__ int sh[64];
    sh[t] = v;
    __syncthreads();
    for (int o = 1; o < 64; o <<= 1) {
        int u = (t >= o) ? sh[t - o] : 0;
        __syncthreads();
        sh[t] += u;
        __syncthreads();
    }
    if (t < NB) g_boff[t] = sh[t] - v;  // exclusive
    if (t == 63) g_rowptr[N] = sh[63];
}

// ---------------- scan phase 3: per-block rescan, write rowptr/fill --------
__global__ void __launch_bounds__(256) k_scan3(int N) {
    int b = blockIdx.x, t = threadIdx.x;
    int lane = t & 31, w = t >> 5;
    int i0 = b * SCHUNK + t * 4;
    int c[4];
    int s = 0;
#pragma unroll
    for (int j = 0; j < 4; ++j) {
        int i = i0 + j;
        c[j] = (i < N) ? g_incnt[i] : 0;
        s += c[j];
    }
    int pre = s;
#pragma unroll
    for (int o = 1; o < 32; o <<= 1) {
        int u = __shfl_up_sync(~0u, pre, o);
        if (lane >= o) pre += u;
    }
    __shared__ int wsum[8];
    if (lane == 31) wsum[w] = pre;
    __syncthreads();
    if (t < 8) {
        int v = wsum[t];
#pragma unroll
        for (int o = 1; o < 8; o <<= 1) {
            int u = __shfl_up_sync(0xffu, v, o);
            if ((int)t >= o) v += u;
        }
        wsum[t] = v;
    }
    __syncthreads();
    int base = g_boff[b] + (w ? wsum[w - 1] : 0) + (pre - s);
#pragma unroll
    for (int j = 0; j < 4; ++j) {
        int i = i0 + j;
        if (i < N) {
            g_rowptr[i] = base;
            g_fill[i]   = base;
            base += c[j];
        }
    }
}

// ---------------- CSR placement ----------------
__global__ void k_fill(const int* __restrict__ src, const int* __restrict__ dst, int E) {
    int i = blockIdx.x * blockDim.x + threadIdx.x;
    if (i < E) {
        int d = dst[i];
        int p = atomicAdd(&g_fill[d], 1);
        g_col[p] = src[i];
    }
}

// ---------------- hi/lo split helpers ----------------
__device__ __forceinline__ void split_bf(float v, __nv_bfloat16& hi, __nv_bfloat16& lo) {
    hi = __float2bfloat16_rn(v);
    lo = __float2bfloat16_rn(v - __bfloat162float(hi));
}
__device__ __forceinline__ unsigned pack2(__nv_bfloat16 a, __nv_bfloat16 b) {
    return ((unsigned)__bfloat16_as_ushort(b) << 16) | (unsigned)__bfloat16_as_ushort(a);
}

// ---------------- prep: transpose + split weights (small) ----------------
__global__ void k_prepw(const float* __restrict__ Win,
                        const float* __restrict__ Wg0,
                        const float* __restrict__ Wg1,
                        const float* __restrict__ Wg2) {
    int i = blockIdx.x * blockDim.x + threadIdx.x;
    if (i < 128 * KIN) {
        int n = i / KIN, k = i % KIN;
        float v = (k < FIN) ? Win[k * 128 + n] : 0.0f;
        split_bf(v, g_wthi[WT_IN_OFF + i], g_wtlo[WT_IN_OFF + i]);
    } else if (i < 128 * KIN + 3 * 128 * 128) {
        int j = i - 128 * KIN;
        int l = j / (128 * 128);
        int r = j - l * 128 * 128;
        int n = r / 128, k = r % 128;
        const float* W = (l == 0) ? Wg0 : (l == 1) ? Wg1 : Wg2;
        float v = W[k * 128 + n];
        split_bf(v, g_wthi[WT_G_OFF + j], g_wtlo[WT_G_OFF + j]);
    }
}

// ---------------- tensor-core GEMM + bias + SiLU (+outnorm) -> fp16 --------
// MODE 0: A = x[N,FIN] fp32, padded to KP, split in staging.
// MODE 2: A = pre-split bf16 hi/lo buffers (from k_agg).
// out[r,:] = fp16( silu(A @ W + b) * (PREMUL ? outnorm[r] : 1) )
// Block: 256 thr (8 warps = 2M x 4N), tile 64 rows x 128 cols. (R6 config)
__device__ __forceinline__ float silu1(float v) { return v / (1.0f + __expf(-v)); }

__device__ __forceinline__ void mma16816(float* d, const unsigned* a, const unsigned* b) {
    asm volatile(
        "mma.sync.aligned.m16n8k16.row.col.f32.bf16.bf16.f32 "
        "{%0,%1,%2,%3}, {%4,%5,%6,%7}, {%8,%9}, {%0,%1,%2,%3};"
        : "+f"(d[0]), "+f"(d[1]), "+f"(d[2]), "+f"(d[3])
        : "r"(a[0]), "r"(a[1]), "r"(a[2]), "r"(a[3]), "r"(b[0]), "r"(b[1]));
}

template <int KP, int MODE, bool PREMUL>
__global__ void __launch_bounds__(256)
k_mlp(const float* __restrict__ Ax,
      const __nv_bfloat16* __restrict__ Ahi, const __nv_bfloat16* __restrict__ Alo,
      const __nv_bfloat16* __restrict__ Whi, const __nv_bfloat16* __restrict__ Wlo,
      const float* __restrict__ bias, __half* __restrict__ out, int N) {
    constexpr int SW = KP / 2 + 4;             // padded stride in 32-bit words
    constexpr int AW = 64 * SW;
    constexpr int WW = 128 * SW;
    extern __shared__ unsigned sh[];
    unsigned* sAh = sh;
    unsigned* sAl = sh + AW;
    unsigned* sWh = sh + 2 * AW;
    unsigned* sWl = sh + 2 * AW + WW;

    const int tid  = threadIdx.x;
    const int lane = tid & 31;
    const int gid  = lane >> 2;
    const int tig  = lane & 3;
    const int warp = tid >> 5;
    const int wm   = warp & 1;
    const int wn   = warp >> 1;
    const int r0   = blockIdx.x * 64;

    // stage W (transposed [n][k], uint4 = 8 bf16)
    constexpr int ACH = KP / 8;
    for (int i = tid; i < 128 * ACH; i += 256) {
        int n = i / ACH, c = i - n * ACH;
        *reinterpret_cast<uint4*>(sWh + n * SW + c * 4) =
            reinterpret_cast<const uint4*>(Whi + (size_t)n * KP)[c];
        *reinterpret_cast<uint4*>(sWl + n * SW + c * 4) =
            reinterpret_cast<const uint4*>(Wlo + (size_t)n * KP)[c];
    }

    // stage A
    if constexpr (MODE == 0) {
        for (int i = tid; i < 64 * (KP / 2); i += 256) {
            int r = i / (KP / 2), kw = i - r * (KP / 2);
            int k = kw * 2, gr = r0 + r;
            float v0 = 0.f, v1 = 0.f;
            if (gr < N) {
                if (k < FIN)     v0 = Ax[(size_t)gr * FIN + k];
                if (k + 1 < FIN) v1 = Ax[(size_t)gr * FIN + k + 1];
            }
            __nv_bfloat16 h0, l0, h1, l1;
            split_bf(v0, h0, l0); split_bf(v1, h1, l1);
            sAh[r * SW + kw] = pack2(h0, h1);
            sAl[r * SW + kw] = pack2(l0, l1);
        }
    } else {
        for (int i = tid; i < 64 * ACH; i += 256) {
            int r = i / ACH, c = i - r * ACH;
            int gr = r0 + r;
            uint4 vh = make_uint4(0, 0, 0, 0), vl = vh;
            if (gr < N) {
                vh = reinterpret_cast<const uint4*>(Ahi + (size_t)gr * KP)[c];
                vl = reinterpret_cast<const uint4*>(Alo + (size_t)gr * KP)[c];
            }
            *reinterpret_cast<uint4*>(sAh + r * SW + c * 4) = vh;
            *reinterpret_cast<uint4*>(sAl + r * SW + c * 4) = vl;
        }
    }
    __syncthreads();

    float d[2][4][4];
#pragma unroll
    for (int nt = 0; nt < 4; ++nt) {
        int c = wn * 32 + nt * 8 + tig * 2;
        float b0 = bias[c], b1 = bias[c + 1];
#pragma unroll
        for (int mi = 0; mi < 2; ++mi) {
            d[mi][nt][0] = b0; d[mi][nt][1] = b1;
            d[mi][nt][2] = b0; d[mi][nt][3] = b1;
        }
    }

#pragma unroll
    for (int ks = 0; ks < KP / 16; ++ks) {
        unsigned ah[2][4], al[2][4];
#pragma unroll
        for (int mi = 0; mi < 2; ++mi) {
            int rr = wm * 32 + mi * 16 + gid;
            int base = ks * 8 + tig;
            ah[mi][0] = sAh[rr * SW + base];
            ah[mi][1] = sAh[(rr + 8) * SW + base];
            ah[mi][2] = sAh[rr * SW + base + 4];
            ah[mi][3] = sAh[(rr + 8) * SW + base + 4];
            al[mi][0] = sAl[rr * SW + base];
            al[mi][1] = sAl[(rr + 8) * SW + base];
            al[mi][2] = sAl[rr * SW + base + 4];
            al[mi][3] = sAl[(rr + 8) * SW + base + 4];
        }
#pragma unroll
        for (int nt = 0; nt < 4; ++nt) {
            int n = wn * 32 + nt * 8 + gid;
            int base = n * SW + ks * 8 + tig;
            unsigned bh[2], bl[2];
            bh[0] = sWh[base]; bh[1] = sWh[base + 4];
            bl[0] = sWl[base]; bl[1] = sWl[base + 4];
#pragma unroll
            for (int mi = 0; mi < 2; ++mi) {
                mma16816(d[mi][nt], ah[mi], bh);
                mma16816(d[mi][nt], ah[mi], bl);
                mma16816(d[mi][nt], al[mi], bh);
            }
        }
    }

    // epilogue: silu (+outnorm premul) + store fp16
#pragma unroll
    for (int mi = 0; mi < 2; ++mi) {
        int r1 = r0 + wm * 32 + mi * 16 + gid;
        int r2 = r1 + 8;
        float on1 = 1.f, on2 = 1.f;
        if (PREMUL) {
            if (r1 < N) on1 = g_outnorm[r1];
            if (r2 < N) on2 = g_outnorm[r2];
        }
#pragma unroll
        for (int nt = 0; nt < 4; ++nt) {
            int c = wn * 32 + nt * 8 + tig * 2;
            if (r1 < N) {
                __half2 v = __floats2half2_rn(silu1(d[mi][nt][0]) * on1,
                                              silu1(d[mi][nt][1]) * on1);
                *reinterpret_cast<__half2*>(out + (size_t)r1 * 128 + c) = v;
            }
            if (r2 < N) {
                __half2 v = __floats2half2_rn(silu1(d[mi][nt][2]) * on2,
                                              silu1(d[mi][nt][3]) * on2);
                *reinterpret_cast<__half2*>(out + (size_t)r2 * 128 + c) = v;
            }
        }
    }
}

// ---------------- gather-aggregate (fp16 in) -> bf16 hi/lo -----------------
// A[w,:] = innorm[w] * sum_{e in row w} h[col[e], :]   (outnorm pre-applied)
__global__ void k_agg(const __half* __restrict__ h, int N) {
    int w = (blockIdx.x * blockDim.x + threadIdx.x) >> 5;
    int lane = threadIdx.x & 31;
    if (w >= N) return;
    int e0 = g_rowptr[w], e1 = g_rowptr[w + 1];
    const uint2* hu = reinterpret_cast<const uint2*>(h);  // 4 halves per lane
    float4 a0 = make_float4(0.f, 0.f, 0.f, 0.f);
    float4 a1 = a0;
    int e = e0;
    for (; e + 1 < e1; e += 2) {
        int s0 = g_col[e], s1 = g_col[e + 1];
        uint2 u0 = hu[(size_t)s0 * 32 + lane];
        uint2 u1 = hu[(size_t)s1 * 32 + lane];
        float2 p0 = __half22float2(*reinterpret_cast<__half2*>(&u0.x));
        float2 p1 = __half22float2(*reinterpret_cast<__half2*>(&u0.y));
        float2 q0 = __half22float2(*reinterpret_cast<__half2*>(&u1.x));
        float2 q1 = __half22float2(*reinterpret_cast<__half2*>(&u1.y));
        a0.x += p0.x; a0.y += p0.y; a0.z += p1.x; a0.w += p1.y;
        a1.x += q0.x; a1.y += q0.y; a1.z += q1.x; a1.w += q1.y;
    }
    if (e < e1) {
        int s = g_col[e];
        uint2 u = hu[(size_t)s * 32 + lane];
        float2 p0 = __half22float2(*reinterpret_cast<__half2*>(&u.x));
        float2 p1 = __half22float2(*reinterpret_cast<__half2*>(&u.y));
        a0.x += p0.x; a0.y += p0.y; a0.z += p1.x; a0.w += p1.y;
    }
    float inn = g_innorm[w];
    float o[4] = {(a0.x + a1.x) * inn, (a0.y + a1.y) * inn,
                  (a0.z + a1.z) * inn, (a0.w + a1.w) * inn};
    __nv_bfloat16 hi[4], lo[4];
#pragma unroll
    for (int j = 0; j < 4; ++j) split_bf(o[j], hi[j], lo[j]);
    size_t base = (size_t)w * 128 + lane * 4;
    *reinterpret_cast<__nv_bfloat162*>(g_ahi + base)     = __nv_bfloat162(hi[0], hi[1]);
    *reinterpret_cast<__nv_bfloat162*>(g_ahi + base + 2) = __nv_bfloat162(hi[2], hi[3]);
    *reinterpret_cast<__nv_bfloat162*>(g_alo + base)     = __nv_bfloat162(lo[0], lo[1]);
    *reinterpret_cast<__nv_bfloat162*>(g_alo + base + 2) = __nv_bfloat162(lo[2], lo[3]);
}

// ---------------- segment-sum pooling (graph_ids sorted, fp16 in) ----------
__global__ void k_pool(const __half* __restrict__ h, const int* __restrict__ gid, int N) {
    int r0 = blockIdx.x * 128;
    if (r0 >= N) return;
    int r1 = r0 + 128; if (r1 > N) r1 = N;
    int j = threadIdx.x;
    int cur = gid[r0];
    float acc = 0.0f;
    int run = 0;
    for (int r = r0; r < r1; ++r) {
        int g = gid[r];
        if (g != cur) {
            atomicAdd(&g_pooled[cur * HDIM + j], acc);
            if (j == 0) atomicAdd(&g_gcnt[cur], run);
            acc = 0.0f; run = 0; cur = g;
        }
        acc += __half2float(h[(size_t)r * HDIM + j]);
        ++run;
    }
    atomicAdd(&g_pooled[cur * HDIM + j], acc);
    if (j == 0) atomicAdd(&g_gcnt[cur], run);
}

// ---------------- final: (pooled @ W_out + cnt*b_out) @ W_ff + b_ff ----------
__global__ void k_final(const float* __restrict__ Wout, const float* __restrict__ bout,
                        const float* __restrict__ Wff, const float* __restrict__ bff,
                        float* __restrict__ out) {
    __shared__ float p[HDIM];
    __shared__ float red[HDIM];
    int g = blockIdx.x, j = threadIdx.x;
    p[j] = g_pooled[g * HDIM + j];
    __syncthreads();
    float t = (float)g_gcnt[g] * bout[j];
#pragma unroll 8
    for (int k = 0; k < HDIM; ++k)
        t = fmaf(p[k], Wout[k * HDIM + j], t);
    red[j] = t * Wff[j];
    __syncthreads();
    for (int s = 64; s > 0; s >>= 1) {
        if (j < s) red[j] += red[j + s];
        __syncthreads();
    }
    if (j == 0) out[g] = red[0] + bff[0];
}

// ---------------- launch ----------------
extern "C" void kernel_launch(void* const* d_in, const int* in_sizes, int n_in,
                              void* d_out, int out_size) {
    const float* x     = (const float*)d_in[0];
    const float* W_in  = (const float*)d_in[1];
    const float* b_in  = (const float*)d_in[2];
    const float* W_g0  = (const float*)d_in[3];
    const float* b_g0  = (const float*)d_in[4];
    const float* W_g1  = (const float*)d_in[5];
    const float* b_g1  = (const float*)d_in[6];
    const float* W_g2  = (const float*)d_in[7];
    const float* b_g2  = (const float*)d_in[8];
    const float* W_out = (const float*)d_in[9];
    const float* b_out = (const float*)d_in[10];
    const float* W_ff  = (const float*)d_in[11];
    const float* b_ff  = (const float*)d_in[12];
    const int*   src   = (const int*)d_in[13];
    const int*   dst   = (const int*)d_in[14];
    const int*   gids  = (const int*)d_in[15];
    float* out = (float*)d_out;

    const int N = in_sizes[0] / FIN;
    const int E = in_sizes[13];
    const int NB = (N + SCHUNK - 1) / SCHUNK;

    __half *h0, *h1;
    __nv_bfloat16 *ahi, *alo, *whi, *wlo;
    cudaGetSymbolAddress((void**)&h0, g_h0);
    cudaGetSymbolAddress((void**)&h1, g_h1);
    cudaGetSymbolAddress((void**)&ahi, g_ahi);
    cudaGetSymbolAddress((void**)&alo, g_alo);
    cudaGetSymbolAddress((void**)&whi, g_wthi);
    cudaGetSymbolAddress((void**)&wlo, g_wtlo);

    const int SW80  = KIN / 2 + 4;
    const int SW128 = HDIM / 2 + 4;
    const size_t shm80  = (size_t)(2 * 64 * SW80 + 2 * 128 * SW80) * 4;    // ~67.5 KB
    const size_t shm128 = (size_t)(2 * 64 * SW128 + 2 * 128 * SW128) * 4;  // ~102 KB
    cudaFuncSetAttribute(k_mlp<KIN, 0, true>,
                         cudaFuncAttributeMaxDynamicSharedMemorySize, (int)shm80);
    cudaFuncSetAttribute(k_mlp<HDIM, 2, true>,
                         cudaFuncAttributeMaxDynamicSharedMemorySize, (int)shm128);
    cudaFuncSetAttribute(k_mlp<HDIM, 2, false>,
                         cudaFuncAttributeMaxDynamicSharedMemorySize, (int)shm128);

    int initMax = (N > NG * HDIM) ? N : NG * HDIM;
    int gemm_blocks = (N + 63) / 64;

    k_prepw<<<(128 * KIN + 3 * 128 * 128 + 255) / 256, 256>>>(W_in, W_g0, W_g1, W_g2); // 0
    k_init<<<(initMax + 255) / 256, 256>>>(N);                                         // 1
    k_hist<<<(E + 255) / 256, 256>>>(src, dst, E);                                     // 2
    k_scan1<<<NB, 256>>>(N);                                                           // 3
    k_scan2<<<1, 64>>>(NB, N);                                                         // 4
    // embedding_in at slot 5 (ncu -s 5 -c 1 lands here): h0 = silu(x@Win+b)*outnorm
    k_mlp<KIN, 0, true><<<gemm_blocks, 256, shm80>>>(
        x, nullptr, nullptr, whi + WT_IN_OFF, wlo + WT_IN_OFF, b_in, h0, N);           // 5
    k_scan3<<<NB, 256>>>(N);                                                           // 6
    k_fill<<<(E + 255) / 256, 256>>>(src, dst, E);                                     // 7

    const float* bg[3] = {b_g0, b_g1, b_g2};
    __half* hin[3]  = {h0, h1, h0};
    __half* hout[3] = {h1, h0, h1};
    int agg_blocks = (N * 32 + 255) / 256;
    for (int l = 0; l < 3; ++l) {
        k_agg<<<agg_blocks, 256>>>(hin[l], N);
        if (l < 2)
            k_mlp<HDIM, 2, true><<<gemm_blocks, 256, shm128>>>(
                nullptr, ahi, alo, whi + WT_G_OFF + l * 128 * 128,
                wlo + WT_G_OFF + l * 128 * 128, bg[l], hout[l], N);
        else
            k_mlp<HDIM, 2, false><<<gemm_blocks, 256, shm128>>>(
                nullptr, ahi, alo, whi + WT_G_OFF + l * 128 * 128,
                wlo + WT_G_OFF + l * 128 * 128, bg[l], hout[l], N);
    }

    k_pool<<<(N + 127) / 128, 128>>>(h1, gids, N);
    k_final<<<NG, HDIM>>>(W_out, b_out, W_ff, b_ff, out);
}

// round 16
// speedup vs baseline: 1.0789x; 1.0727x over previous
#include <cuda_runtime.h>
#include <cuda_bf16.h>
#include <cuda_fp16.h>
#include <math.h>

// Problem constants
#define NMAX   50000
#define EMAX   600000
#define FIN    74
#define KIN    80          // FIN padded to multiple of 16
#define HDIM   128
#define NG     500
#define SCHUNK 1024        // nodes per scan block
#define NBMAX  64

// ---------------- scratch (device globals) ----------------
__device__ __align__(16) __half g_h0[NMAX * HDIM];   // node features ping (fp16)
__device__ __align__(16) __half g_h1[NMAX * HDIM];   // node features pong (fp16)
__device__ __align__(16) __half g_a[NMAX * HDIM];    // aggregated A operand (fp16)
// transposed weights (fp16 hi/lo): Wt[n][k]. in: 128*80, g0/g1/g2: 128*128 each
#define WT_IN_OFF  0
#define WT_G_OFF   (128*KIN)
#define WT_TOTAL   (128*KIN + 3*128*128)
__device__ __align__(16) __half g_wthi[WT_TOTAL];
__device__ __align__(16) __half g_wtlo[WT_TOTAL];

__device__ int   g_outcnt[NMAX];
__device__ int   g_incnt[NMAX];
__device__ int   g_rowptr[NMAX + 1];
__device__ int   g_fill[NMAX];
__device__ int   g_col[EMAX];
__device__ float g_outnorm[NMAX];
__device__ float g_innorm[NMAX];
__device__ __align__(16) float g_pooled[NG * HDIM];
__device__ int   g_gcnt[NG];
__device__ int   g_bsum[NBMAX];
__device__ int   g_boff[NBMAX];

// ---------------- init ----------------
__global__ void k_init(int N) {
    int i = blockIdx.x * blockDim.x + threadIdx.x;
    if (i < N) { g_outcnt[i] = 0; g_incnt[i] = 0; }
    if (i < NG * HDIM) g_pooled[i] = 0.0f;
    if (i < NG) g_gcnt[i] = 0;
}

// ---------------- degree histogram ----------------
__global__ void k_hist(const int* __restrict__ src, const int* __restrict__ dst, int E) {
    int i = blockIdx.x * blockDim.x + threadIdx.x;
    if (i < E) {
        atomicAdd(&g_outcnt[src[i]], 1);
        atomicAdd(&g_incnt[dst[i]], 1);
    }
}

// ---------------- parallel scan, phase 1: per-block reduce + norms ----------
__global__ void __launch_bounds__(256) k_scan1(int N) {
    int b = blockIdx.x, t = threadIdx.x;
    int i0 = b * SCHUNK + t * 4;
    int s = 0;
#pragma unroll
    for (int j = 0; j < 4; ++j) {
        int i = i0 + j;
        if (i < N) {
            int c = g_incnt[i];
            s += c;
            g_innorm[i] = rsqrtf((float)(c > 0 ? c : 1));
            int oc = g_outcnt[i];
            g_outnorm[i] = rsqrtf((float)(oc > 0 ? oc : 1));
        }
    }
    __shared__ int red[8];
#pragma unroll
    for (int o = 16; o; o >>= 1) s += __shfl_down_sync(~0u, s, o);
    if ((t & 31) == 0) red[t >> 5] = s;
    __syncthreads();
    if (t < 8) {
        int v = red[t];
#pragma unroll
        for (int o = 4; o; o >>= 1) v += __shfl_down_sync(0xffu, v, o);
        if (t == 0) g_bsum[b] = v;
    }
}

// ---------------- scan phase 2: scan block sums (tiny) ----------------
__global__ void k_scan2(int NB, int N) {
    int t = threadIdx.x;  // 64 threads
    int v = (t < NB) ? g_bsum[t] : 0;
    __shared__ int sh[64];
    sh[t] = v;
    __syncthreads();
    for (int o = 1; o < 64; o <<= 1) {
        int u = (t >= o) ? sh[t - o] : 0;
        __syncthreads();
        sh[t] += u;
        __syncthreads();
    }
    if (t < NB) g_boff[t] = sh[t] - v;  // exclusive
    if (t == 63) g_rowptr[N] = sh[63];
}

// ---------------- scan phase 3: per-block rescan, write rowptr/fill --------
__global__ void __launch_bounds__(256) k_scan3(int N) {
    int b = blockIdx.x, t = threadIdx.x;
    int lane = t & 31, w = t >> 5;
    int i0 = b * SCHUNK + t * 4;
    int c[4];
    int s = 0;
#pragma unroll
    for (int j = 0; j < 4; ++j) {
        int i = i0 + j;
        c[j] = (i < N) ? g_incnt[i] : 0;
        s += c[j];
    }
    int pre = s;
#pragma unroll
    for (int o = 1; o < 32; o <<= 1) {
        int u = __shfl_up_sync(~0u, pre, o);
        if (lane >= o) pre += u;
    }
    __shared__ int wsum[8];
    if (lane == 31) wsum[w] = pre;
    __syncthreads();
    if (t < 8) {
        int v = wsum[t];
#pragma unroll
        for (int o = 1; o < 8; o <<= 1) {
            int u = __shfl_up_sync(0xffu, v, o);
            if ((int)t >= o) v += u;
        }
        wsum[t] = v;
    }
    __syncthreads();
    int base = g_boff[b] + (w ? wsum[w - 1] : 0) + (pre - s);
#pragma unroll
    for (int j = 0; j < 4; ++j) {
        int i = i0 + j;
        if (i < N) {
            g_rowptr[i] = base;
            g_fill[i]   = base;
            base += c[j];
        }
    }
}

// ---------------- CSR placement ----------------
__global__ void k_fill(const int* __restrict__ src, const int* __restrict__ dst, int E) {
    int i = blockIdx.x * blockDim.x + threadIdx.x;
    if (i < E) {
        int d = dst[i];
        int p = atomicAdd(&g_fill[d], 1);
        g_col[p] = src[i];
    }
}

// ---------------- fp16 split helper (W is near-exact in hi+lo) -------------
__device__ __forceinline__ void split_h(float v, __half& hi, __half& lo) {
    hi = __float2half_rn(v);
    lo = __float2half_rn(v - __half2float(hi));
}

// ---------------- prep: transpose + split weights (small) ----------------
__global__ void k_prepw(const float* __restrict__ Win,
                        const float* __restrict__ Wg0,
                        const float* __restrict__ Wg1,
                        const float* __restrict__ Wg2) {
    int i = blockIdx.x * blockDim.x + threadIdx.x;
    if (i < 128 * KIN) {
        int n = i / KIN, k = i % KIN;
        float v = (k < FIN) ? Win[k * 128 + n] : 0.0f;
        split_h(v, g_wthi[WT_IN_OFF + i], g_wtlo[WT_IN_OFF + i]);
    } else if (i < 128 * KIN + 3 * 128 * 128) {
        int j = i - 128 * KIN;
        int l = j / (128 * 128);
        int r = j - l * 128 * 128;
        int n = r / 128, k = r % 128;
        const float* W = (l == 0) ? Wg0 : (l == 1) ? Wg1 : Wg2;
        float v = W[k * 128 + n];
        split_h(v, g_wthi[WT_G_OFF + j], g_wtlo[WT_G_OFF + j]);
    }
}

// ---------------- tensor-core GEMM + bias + SiLU (+outnorm) -> fp16 --------
// MODE 0: A = x[N,FIN] fp32 -> fp16 in staging, padded to KP.
// MODE 2: A = g_a fp16 (from k_agg).
// out[r,:] = fp16( silu(A @ (Whi+Wlo) + b) * (PREMUL ? outnorm[r] : 1) )
// Block: 256 thr (8 warps = 2M x 4N), tile 64 rows x 128 cols.
__device__ __forceinline__ float silu1(float v) { return v / (1.0f + __expf(-v)); }

__device__ __forceinline__ void mma16816h(float* d, const unsigned* a, const unsigned* b) {
    asm volatile(
        "mma.sync.aligned.m16n8k16.row.col.f32.f16.f16.f32 "
        "{%0,%1,%2,%3}, {%4,%5,%6,%7}, {%8,%9}, {%0,%1,%2,%3};"
        : "+f"(d[0]), "+f"(d[1]), "+f"(d[2]), "+f"(d[3])
        : "r"(a[0]), "r"(a[1]), "r"(a[2]), "r"(a[3]), "r"(b[0]), "r"(b[1]));
}

template <int KP, int MODE, bool PREMUL>
__global__ void __launch_bounds__(256)
k_mlp(const float* __restrict__ Ax, const __half* __restrict__ Aq,
      const __half* __restrict__ Whi, const __half* __restrict__ Wlo,
      const float* __restrict__ bias, __half* __restrict__ out, int N) {
    constexpr int SW = KP / 2 + 4;             // padded stride in 32-bit words
    constexpr int AW = 64 * SW;
    constexpr int WW = 128 * SW;
    extern __shared__ unsigned sh[];
    unsigned* sA  = sh;
    unsigned* sWh = sh + AW;
    unsigned* sWl = sh + AW + WW;

    const int tid  = threadIdx.x;
    const int lane = tid & 31;
    const int gid  = lane >> 2;
    const int tig  = lane & 3;
    const int warp = tid >> 5;
    const int wm   = warp & 1;
    const int wn   = warp >> 1;
    const int r0   = blockIdx.x * 64;

    // stage W (transposed [n][k], uint4 = 8 fp16)
    constexpr int ACH = KP / 8;
    for (int i = tid; i < 128 * ACH; i += 256) {
        int n = i / ACH, c = i - n * ACH;
        *reinterpret_cast<uint4*>(sWh + n * SW + c * 4) =
            reinterpret_cast<const uint4*>(Whi + (size_t)n * KP)[c];
        *reinterpret_cast<uint4*>(sWl + n * SW + c * 4) =
            reinterpret_cast<const uint4*>(Wlo + (size_t)n * KP)[c];
    }

    // stage A (single fp16)
    if constexpr (MODE == 0) {
        for (int i = tid; i < 64 * (KP / 2); i += 256) {
            int r = i / (KP / 2), kw = i - r * (KP / 2);
            int k = kw * 2, gr = r0 + r;
            float v0 = 0.f, v1 = 0.f;
            if (gr < N) {
                if (k < FIN)     v0 = Ax[(size_t)gr * FIN + k];
                if (k + 1 < FIN) v1 = Ax[(size_t)gr * FIN + k + 1];
            }
            __half2 hh = __floats2half2_rn(v0, v1);
            sA[r * SW + kw] = *reinterpret_cast<unsigned*>(&hh);
        }
    } else {
        for (int i = tid; i < 64 * ACH; i += 256) {
            int r = i / ACH, c = i - r * ACH;
            int gr = r0 + r;
            uint4 v = make_uint4(0, 0, 0, 0);
            if (gr < N) v = reinterpret_cast<const uint4*>(Aq + (size_t)gr * KP)[c];
            *reinterpret_cast<uint4*>(sA + r * SW + c * 4) = v;
        }
    }
    __syncthreads();

    float d[2][4][4];
#pragma unroll
    for (int nt = 0; nt < 4; ++nt) {
        int c = wn * 32 + nt * 8 + tig * 2;
        float b0 = bias[c], b1 = bias[c + 1];
#pragma unroll
        for (int mi = 0; mi < 2; ++mi) {
            d[mi][nt][0] = b0; d[mi][nt][1] = b1;
            d[mi][nt][2] = b0; d[mi][nt][3] = b1;
        }
    }

#pragma unroll
    for (int ks = 0; ks < KP / 16; ++ks) {
        unsigned a[2][4];
#pragma unroll
        for (int mi = 0; mi < 2; ++mi) {
            int rr = wm * 32 + mi * 16 + gid;
            int base = ks * 8 + tig;
            a[mi][0] = sA[rr * SW + base];
            a[mi][1] = sA[(rr + 8) * SW + base];
            a[mi][2] = sA[rr * SW + base + 4];
            a[mi][3] = sA[(rr + 8) * SW + base + 4];
        }
#pragma unroll
        for (int nt = 0; nt < 4; ++nt) {
            int n = wn * 32 + nt * 8 + gid;
            int base = n * SW + ks * 8 + tig;
            unsigned bh[2], bl[2];
            bh[0] = sWh[base]; bh[1] = sWh[base + 4];
            bl[0] = sWl[base]; bl[1] = sWl[base + 4];
#pragma unroll
            for (int mi = 0; mi < 2; ++mi) {
                mma16816h(d[mi][nt], a[mi], bh);
                mma16816h(d[mi][nt], a[mi], bl);
            }
        }
    }

    // epilogue: silu (+outnorm premul) + store fp16
#pragma unroll
    for (int mi = 0; mi < 2; ++mi) {
        int r1 = r0 + wm * 32 + mi * 16 + gid;
        int r2 = r1 + 8;
        float on1 = 1.f, on2 = 1.f;
        if (PREMUL) {
            if (r1 < N) on1 = g_outnorm[r1];
            if (r2 < N) on2 = g_outnorm[r2];
        }
#pragma unroll
        for (int nt = 0; nt < 4; ++nt) {
            int c = wn * 32 + nt * 8 + tig * 2;
            if (r1 < N) {
                __half2 v = __floats2half2_rn(silu1(d[mi][nt][0]) * on1,
                                              silu1(d[mi][nt][1]) * on1);
                *reinterpret_cast<__half2*>(out + (size_t)r1 * 128 + c) = v;
            }
            if (r2 < N) {
                __half2 v = __floats2half2_rn(silu1(d[mi][nt][2]) * on2,
                                              silu1(d[mi][nt][3]) * on2);
                *reinterpret_cast<__half2*>(out + (size_t)r2 * 128 + c) = v;
            }
        }
    }
}

// ---------------- gather-aggregate (fp16 in) -> fp16 A ---------------------
// A[w,:] = fp16( innorm[w] * sum_{e in row w} h[col[e], :] )  (outnorm pre-applied)
__global__ void k_agg(const __half* __restrict__ h, int N) {
    int w = (blockIdx.x * blockDim.x + threadIdx.x) >> 5;
    int lane = threadIdx.x & 31;
    if (w >= N) return;
    int e0 = g_rowptr[w], e1 = g_rowptr[w + 1];
    const uint2* hu = reinterpret_cast<const uint2*>(h);  // 4 halves per lane
    float4 a0 = make_float4(0.f, 0.f, 0.f, 0.f);
    float4 a1 = a0;
    int e = e0;
    for (; e + 1 < e1; e += 2) {
        int s0 = g_col[e], s1 = g_col[e + 1];
        uint2 u0 = hu[(size_t)s0 * 32 + lane];
        uint2 u1 = hu[(size_t)s1 * 32 + lane];
        float2 p0 = __half22float2(*reinterpret_cast<__half2*>(&u0.x));
        float2 p1 = __half22float2(*reinterpret_cast<__half2*>(&u0.y));
        float2 q0 = __half22float2(*reinterpret_cast<__half2*>(&u1.x));
        float2 q1 = __half22float2(*reinterpret_cast<__half2*>(&u1.y));
        a0.x += p0.x; a0.y += p0.y; a0.z += p1.x; a0.w += p1.y;
        a1.x += q0.x; a1.y += q0.y; a1.z += q1.x; a1.w += q1.y;
    }
    if (e < e1) {
        int s = g_col[e];
        uint2 u = hu[(size_t)s * 32 + lane];
        float2 p0 = __half22float2(*reinterpret_cast<__half2*>(&u.x));
        float2 p1 = __half22float2(*reinterpret_cast<__half2*>(&u.y));
        a0.x += p0.x; a0.y += p0.y; a0.z += p1.x; a0.w += p1.y;
    }
    float inn = g_innorm[w];
    __half2 o0 = __floats2half2_rn((a0.x + a1.x) * inn, (a0.y + a1.y) * inn);
    __half2 o1 = __floats2half2_rn((a0.z + a1.z) * inn, (a0.w + a1.w) * inn);
    uint2 pk;
    pk.x = *reinterpret_cast<unsigned*>(&o0);
    pk.y = *reinterpret_cast<unsigned*>(&o1);
    reinterpret_cast<uint2*>(g_a)[(size_t)w * 32 + lane] = pk;
}

// ---------------- segment-sum pooling (graph_ids sorted, fp16 in) ----------
__global__ void k_pool(const __half* __restrict__ h, const int* __restrict__ gid, int N) {
    int r0 = blockIdx.x * 128;
    if (r0 >= N) return;
    int r1 = r0 + 128; if (r1 > N) r1 = N;
    int j = threadIdx.x;
    int cur = gid[r0];
    float acc = 0.0f;
    int run = 0;
    for (int r = r0; r < r1; ++r) {
        int g = gid[r];
        if (g != cur) {
            atomicAdd(&g_pooled[cur * HDIM + j], acc);
            if (j == 0) atomicAdd(&g_gcnt[cur], run);
            acc = 0.0f; run = 0; cur = g;
        }
        acc += __half2float(h[(size_t)r * HDIM + j]);
        ++run;
    }
    atomicAdd(&g_pooled[cur * HDIM + j], acc);
    if (j == 0) atomicAdd(&g_gcnt[cur], run);
}

// ---------------- final: (pooled @ W_out + cnt*b_out) @ W_ff + b_ff ----------
__global__ void k_final(const float* __restrict__ Wout, const float* __restrict__ bout,
                        const float* __restrict__ Wff, const float* __restrict__ bff,
                        float* __restrict__ out) {
    __shared__ float p[HDIM];
    __shared__ float red[HDIM];
    int g = blockIdx.x, j = threadIdx.x;
    p[j] = g_pooled[g * HDIM + j];
    __syncthreads();
    float t = (float)g_gcnt[g] * bout[j];
#pragma unroll 8
    for (int k = 0; k < HDIM; ++k)
        t = fmaf(p[k], Wout[k * HDIM + j], t);
    red[j] = t * Wff[j];
    __syncthreads();
    for (int s = 64; s > 0; s >>= 1) {
        if (j < s) red[j] += red[j + s];
        __syncthreads();
    }
    if (j == 0) out[g] = red[0] + bff[0];
}

// ---------------- launch ----------------
extern "C" void kernel_launch(void* const* d_in, const int* in_sizes, int n_in,
                              void* d_out, int out_size) {
    const float* x     = (const float*)d_in[0];
    const float* W_in  = (const float*)d_in[1];
    const float* b_in  = (const float*)d_in[2];
    const float* W_g0  = (const float*)d_in[3];
    const float* b_g0  = (const float*)d_in[4];
    const float* W_g1  = (const float*)d_in[5];
    const float* b_g1  = (const float*)d_in[6];
    const float* W_g2  = (const float*)d_in[7];
    const float* b_g2  = (const float*)d_in[8];
    const float* W_out = (const float*)d_in[9];
    const float* b_out = (const float*)d_in[10];
    const float* W_ff  = (const float*)d_in[11];
    const float* b_ff  = (const float*)d_in[12];
    const int*   src   = (const int*)d_in[13];
    const int*   dst   = (const int*)d_in[14];
    const int*   gids  = (const int*)d_in[15];
    float* out = (float*)d_out;

    const int N = in_sizes[0] / FIN;
    const int E = in_sizes[13];
    const int NB = (N + SCHUNK - 1) / SCHUNK;

    __half *h0, *h1, *aq, *whi, *wlo;
    cudaGetSymbolAddress((void**)&h0, g_h0);
    cudaGetSymbolAddress((void**)&h1, g_h1);
    cudaGetSymbolAddress((void**)&aq, g_a);
    cudaGetSymbolAddress((void**)&whi, g_wthi);
    cudaGetSymbolAddress((void**)&wlo, g_wtlo);

    const int SW80  = KIN / 2 + 4;
    const int SW128 = HDIM / 2 + 4;
    const size_t shm80  = (size_t)(64 * SW80 + 2 * 128 * SW80) * 4;    // ~56 KB
    const size_t shm128 = (size_t)(64 * SW128 + 2 * 128 * SW128) * 4;  // ~87 KB
    cudaFuncSetAttribute(k_mlp<KIN, 0, true>,
                         cudaFuncAttributeMaxDynamicSharedMemorySize, (int)shm80);
    cudaFuncSetAttribute(k_mlp<HDIM, 2, true>,
                         cudaFuncAttributeMaxDynamicSharedMemorySize, (int)shm128);
    cudaFuncSetAttribute(k_mlp<HDIM, 2, false>,
                         cudaFuncAttributeMaxDynamicSharedMemorySize, (int)shm128);

    int initMax = (N > NG * HDIM) ? N : NG * HDIM;
    int gemm_blocks = (N + 63) / 64;

    k_prepw<<<(128 * KIN + 3 * 128 * 128 + 255) / 256, 256>>>(W_in, W_g0, W_g1, W_g2); // 0
    k_init<<<(initMax + 255) / 256, 256>>>(N);                                         // 1
    k_hist<<<(E + 255) / 256, 256>>>(src, dst, E);                                     // 2
    k_scan1<<<NB, 256>>>(N);                                                           // 3
    k_scan2<<<1, 64>>>(NB, N);                                                         // 4
    // embedding_in at slot 5 (ncu -s 5 -c 1 lands here): h0 = silu(x@Win+b)*outnorm
    k_mlp<KIN, 0, true><<<gemm_blocks, 256, shm80>>>(
        x, nullptr, whi + WT_IN_OFF, wlo + WT_IN_OFF, b_in, h0, N);                    // 5
    k_scan3<<<NB, 256>>>(N);                                                           // 6
    k_fill<<<(E + 255) / 256, 256>>>(src, dst, E);                                     // 7

    const float* bg[3] = {b_g0, b_g1, b_g2};
    __half* hin[3]  = {h0, h1, h0};
    __half* hout[3] = {h1, h0, h1};
    int agg_blocks = (N * 32 + 255) / 256;
    for (int l = 0; l < 3; ++l) {
        k_agg<<<agg_blocks, 256>>>(hin[l], N);
        if (l < 2)
            k_mlp<HDIM, 2, true><<<gemm_blocks, 256, shm128>>>(
                nullptr, aq, whi + WT_G_OFF + l * 128 * 128,
                wlo + WT_G_OFF + l * 128 * 128, bg[l], hout[l], N);
        else
            k_mlp<HDIM, 2, false><<<gemm_blocks, 256, shm128>>>(
                nullptr, aq, whi + WT_G_OFF + l * 128 * 128,
                wlo + WT_G_OFF + l * 128 * 128, bg[l], hout[l], N);
    }

    k_pool<<<(N + 127) / 128, 128>>>(h1, gids, N);
    k_final<<<NG, HDIM>>>(W_out, b_out, W_ff, b_ff, out);
}